// round 1
// baseline (speedup 1.0000x reference)
#include <cuda_runtime.h>

#define BATCH 8
#define H 1024
#define W 1024
#define HW (H*W)

// Per-batch accumulators (tiny scratch; allowed as __device__ globals).
__device__ double g_sum[BATCH];
__device__ double g_sumsq[BATCH];

__global__ void zero_sums_kernel() {
    int i = threadIdx.x;
    if (i < BATCH) { g_sum[i] = 0.0; g_sumsq[i] = 0.0; }
}

// Tile: 128 wide x 16 tall, 512 threads (32x16), each thread does 4 pixels
// at column stride 32 (conflict-free shared reads, coalesced global stores).
#define TW 128
#define TH 16
#define SW (TW + 2)
#define SH (TH + 2)

__global__ __launch_bounds__(512)
void ltpe_pass1(const float* __restrict__ x, float* __restrict__ out) {
    __shared__ float gs[SH][SW];           // 18*130*4 = 9360 B
    __shared__ float wsum[16], wsum2[16];

    const int b  = blockIdx.z;
    const int x0 = blockIdx.x * TW;
    const int y0 = blockIdx.y * TH;
    const int tx = threadIdx.x;
    const int ty = threadIdx.y;
    const int tid = ty * 32 + tx;

    const float* __restrict__ xr = x + (size_t)b * 3 * HW;
    const float* __restrict__ xg = xr + HW;
    const float* __restrict__ xb = xg + HW;

    // Fill shared grayscale tile incl. 1-pixel halo (zero outside image).
    for (int idx = tid; idx < SH * SW; idx += 512) {
        int sr = idx / SW;
        int sc = idx - sr * SW;
        int gy = y0 + sr - 1;
        int gx = x0 + sc - 1;
        float v = 0.0f;
        if (gy >= 0 && gy < H && gx >= 0 && gx < W) {
            int o = gy * W + gx;
            v = 0.3f * xr[o] + 0.59f * xg[o] + 0.11f * xb[o];
        }
        gs[sr][sc] = v;
    }
    __syncthreads();

    // out = 0.5*(g+1) - (0.5/255) * sum_j 2^j * nb_j
    // OFFSETS j=0..7: (0,-1) (1,-1) (1,0) (1,1) (0,1) (-1,1) (-1,0) (-1,-1)
    float s = 0.0f, s2 = 0.0f;
    float* __restrict__ orow = out + (size_t)b * 3 * HW;   // channel-0 slice = scratch
    const int sr = ty + 1;
    const int gy = y0 + ty;

    #pragma unroll
    for (int k = 0; k < 4; k++) {
        const int sc = k * 32 + tx + 1;
        const float g = gs[sr][sc];
        float acc =   1.0f * gs[sr    ][sc - 1]
                    + 2.0f * gs[sr + 1][sc - 1]
                    + 4.0f * gs[sr + 1][sc    ]
                    + 8.0f * gs[sr + 1][sc + 1]
                    + 16.0f * gs[sr    ][sc + 1]
                    + 32.0f * gs[sr - 1][sc + 1]
                    + 64.0f * gs[sr - 1][sc    ]
                    + 128.0f * gs[sr - 1][sc - 1];
        float o = 0.5f * (g + 1.0f) - (0.5f / 255.0f) * acc;
        orow[gy * W + x0 + k * 32 + tx] = o;
        s  += o;
        s2 += o * o;
    }

    // Block reduction: warp shuffle then cross-warp, one double atomic pair.
    #pragma unroll
    for (int off = 16; off > 0; off >>= 1) {
        s  += __shfl_down_sync(0xFFFFFFFFu, s,  off);
        s2 += __shfl_down_sync(0xFFFFFFFFu, s2, off);
    }
    if (tx == 0) { wsum[ty] = s; wsum2[ty] = s2; }
    __syncthreads();
    if (tid == 0) {
        float ts = 0.0f, ts2 = 0.0f;
        #pragma unroll
        for (int w = 0; w < 16; w++) { ts += wsum[w]; ts2 += wsum2[w]; }
        atomicAdd(&g_sum[b],   (double)ts);
        atomicAdd(&g_sumsq[b], (double)ts2);
    }
}

__global__ __launch_bounds__(256)
void ltpe_pass2(float* __restrict__ out) {
    const int b = blockIdx.y;
    const int i = (blockIdx.x * 256 + threadIdx.x) * 4;

    const double dmean = g_sum[b] * (1.0 / HW);
    const double dvar  = g_sumsq[b] * (1.0 / HW) - dmean * dmean;
    const float  m    = (float)dmean;
    const float  rstd = rsqrtf((float)dvar + 1e-5f);

    float* __restrict__ base = out + (size_t)b * 3 * HW;
    float4 v = *(const float4*)(base + i);
    v.x = (v.x - m) * rstd;
    v.y = (v.y - m) * rstd;
    v.z = (v.z - m) * rstd;
    v.w = (v.w - m) * rstd;
    *(float4*)(base + i)          = v;   // channel 0 (overwrite scratch)
    *(float4*)(base + HW + i)     = v;   // channel 1
    *(float4*)(base + 2 * HW + i) = v;   // channel 2
}

extern "C" void kernel_launch(void* const* d_in, const int* in_sizes, int n_in,
                              void* d_out, int out_size) {
    const float* x = (const float*)d_in[0];
    float* out = (float*)d_out;

    zero_sums_kernel<<<1, 32>>>();

    dim3 blk1(32, 16);
    dim3 grd1(W / TW, H / TH, BATCH);
    ltpe_pass1<<<grd1, blk1>>>(x, out);

    dim3 grd2(HW / 4 / 256, BATCH);
    ltpe_pass2<<<grd2, 256>>>(out);
}

// round 4
// speedup vs baseline: 1.2264x; 1.2264x over previous
#include <cuda_runtime.h>

#define BATCH 8
#define H 1024
#define W 1024
#define HW (H*W)

// Pass-1 tiling: 256 wide x 8 tall, 512 threads = (64,8), 4 px/thread (float4)
#define TW 256
#define TH 8
#define SW (TW + 2)          // 258
#define SH (TH + 2)          // 10
#define BLKX (W / TW)        // 4
#define BLKY (H / TH)        // 128
#define PBLK (BLKX * BLKY)   // 512 partials per batch

// Per-block partial sums (s, s2). Every slot is rewritten every launch -> no zeroing needed.
__device__ float2 g_part[BATCH * PBLK];

__global__ __launch_bounds__(512)
void ltpe_pass1(const float* __restrict__ x, float* __restrict__ out) {
    __shared__ float gs[SH][SW];
    __shared__ float2 wred[16];

    const int b  = blockIdx.z;
    const int x0 = blockIdx.x * TW;
    const int y0 = blockIdx.y * TH;
    const int tx = threadIdx.x;          // 0..63
    const int ty = threadIdx.y;          // 0..7
    const int tid = ty * 64 + tx;

    const float* __restrict__ xr = x + (size_t)b * 3 * HW;
    const float* __restrict__ xg = xr + HW;
    const float* __restrict__ xb = xg + HW;

    // ---- Interior: vectorized loads, evict-first (x is read exactly once) ----
    {
        const int gy = y0 + ty;
        const int gx = x0 + 4 * tx;
        const int o  = gy * W + gx;
        float4 r4 = __ldcs((const float4*)(xr + o));
        float4 g4 = __ldcs((const float4*)(xg + o));
        float4 b4 = __ldcs((const float4*)(xb + o));
        const int sr = ty + 1;
        const int sc = 1 + 4 * tx;
        gs[sr][sc + 0] = 0.3f * r4.x + 0.59f * g4.x + 0.11f * b4.x;
        gs[sr][sc + 1] = 0.3f * r4.y + 0.59f * g4.y + 0.11f * b4.y;
        gs[sr][sc + 2] = 0.3f * r4.z + 0.59f * g4.z + 0.11f * b4.z;
        gs[sr][sc + 3] = 0.3f * r4.w + 0.59f * g4.w + 0.11f * b4.w;
    }

    // ---- Halo ring: 2*258 (top/bottom) + 2*8 (left/right) = 532 scalar loads ----
    for (int idx = tid; idx < 2 * SW + 2 * TH; idx += 512) {
        int sr, sc;
        if (idx < SW)              { sr = 0;      sc = idx; }
        else if (idx < 2 * SW)     { sr = SH - 1; sc = idx - SW; }
        else {
            int k = idx - 2 * SW;            // 0..15
            sr = (k & 7) + 1;
            sc = (k < TH) ? 0 : (SW - 1);
        }
        int gy = y0 + sr - 1;
        int gx = x0 + sc - 1;
        float v = 0.0f;
        if (gy >= 0 && gy < H && gx >= 0 && gx < W) {
            int o = gy * W + gx;
            v = 0.3f * __ldcs(xr + o) + 0.59f * __ldcs(xg + o) + 0.11f * __ldcs(xb + o);
        }
        gs[sr][sc] = v;
    }
    __syncthreads();

    // ---- Stencil: out = 0.5*(g+1) - (0.5/255) * sum_j 2^j * nb_j ----
    // weights: top(-1): dj=-1:128, 0:64, +1:32 | mid: -1:1, +1:16 | bot(+1): -1:2, 0:4, +1:8
    float s = 0.0f, s2 = 0.0f;
    {
        const int sr  = ty + 1;
        const int sc0 = 1 + 4 * tx;
        float t[6], m[6], bo[6];
        #pragma unroll
        for (int j = 0; j < 6; j++) {
            t[j]  = gs[sr - 1][sc0 - 1 + j];
            m[j]  = gs[sr    ][sc0 - 1 + j];
            bo[j] = gs[sr + 1][sc0 - 1 + j];
        }
        float4 ov;
        float* op = (float*)&ov;
        #pragma unroll
        for (int k = 0; k < 4; k++) {
            float g   = m[k + 1];
            float acc = 128.0f * t[k]  + 64.0f * t[k + 1] + 32.0f * t[k + 2]
                      +   1.0f * m[k]  + 16.0f * m[k + 2]
                      +   2.0f * bo[k] +  4.0f * bo[k + 1] + 8.0f * bo[k + 2];
            float o = 0.5f * (g + 1.0f) - (0.5f / 255.0f) * acc;
            op[k] = o;
            s  += o;
            s2 += o * o;
        }
        // scratch write: default policy -> stays in L2 for pass 2
        const int gy = y0 + ty;
        *(float4*)(out + (size_t)b * 3 * HW + gy * W + x0 + 4 * tx) = ov;
    }

    // ---- Block reduction -> one float2 partial per block ----
    #pragma unroll
    for (int off = 16; off > 0; off >>= 1) {
        s  += __shfl_down_sync(0xFFFFFFFFu, s,  off);
        s2 += __shfl_down_sync(0xFFFFFFFFu, s2, off);
    }
    if ((tid & 31) == 0) wred[tid >> 5] = make_float2(s, s2);
    __syncthreads();
    if (tid == 0) {
        float ts = 0.0f, ts2 = 0.0f;
        #pragma unroll
        for (int w = 0; w < 16; w++) { ts += wred[w].x; ts2 += wred[w].y; }
        g_part[b * PBLK + blockIdx.y * BLKX + blockIdx.x] = make_float2(ts, ts2);
    }
}

__global__ __launch_bounds__(256)
void ltpe_pass2(float* __restrict__ out) {
    __shared__ double rs[8], rs2[8];
    __shared__ float2 norm;

    const int b   = blockIdx.y;
    const int tid = threadIdx.x;

    // ---- Reduce this batch's 512 partials (L2-resident, 4 KB) ----
    {
        float2 p0 = g_part[b * PBLK + tid];
        float2 p1 = g_part[b * PBLK + tid + 256];
        double s  = (double)p0.x + (double)p1.x;
        double s2 = (double)p0.y + (double)p1.y;
        #pragma unroll
        for (int off = 16; off > 0; off >>= 1) {
            s  += __shfl_down_sync(0xFFFFFFFFu, s,  off);
            s2 += __shfl_down_sync(0xFFFFFFFFu, s2, off);
        }
        if ((tid & 31) == 0) { rs[tid >> 5] = s; rs2[tid >> 5] = s2; }
        __syncthreads();
        if (tid == 0) {
            double ts = 0.0, ts2 = 0.0;
            #pragma unroll
            for (int w = 0; w < 8; w++) { ts += rs[w]; ts2 += rs2[w]; }
            double mean = ts * (1.0 / HW);
            double var  = ts2 * (1.0 / HW) - mean * mean;
            norm = make_float2((float)mean, rsqrtf((float)var + 1e-5f));
        }
        __syncthreads();
    }

    const float m    = norm.x;
    const float rstd = norm.y;
    const int i = (blockIdx.x * 256 + tid) * 4;
    float* __restrict__ base = out + (size_t)b * 3 * HW;

    float4 v = __ldcs((const float4*)(base + i));   // scratch: read once, evict
    v.x = (v.x - m) * rstd;
    v.y = (v.y - m) * rstd;
    v.z = (v.z - m) * rstd;
    v.w = (v.w - m) * rstd;
    __stcs((float4*)(base + i),          v);        // never re-read: stream out
    __stcs((float4*)(base + HW + i),     v);
    __stcs((float4*)(base + 2 * HW + i), v);
}

extern "C" void kernel_launch(void* const* d_in, const int* in_sizes, int n_in,
                              void* d_out, int out_size) {
    const float* x = (const float*)d_in[0];
    float* out = (float*)d_out;

    dim3 blk1(64, 8);
    dim3 grd1(BLKX, BLKY, BATCH);
    ltpe_pass1<<<grd1, blk1>>>(x, out);

    dim3 grd2(HW / 4 / 256, BATCH);
    ltpe_pass2<<<grd2, 256>>>(out);
}

// round 5
// speedup vs baseline: 1.3246x; 1.0801x over previous
#include <cuda_runtime.h>

#define BATCH 8
#define H 1024
#define W 1024
#define HW (H*W)

// Pass-1 tiling: 256 wide x 16 tall, 512 threads = (64,8), 2 rows/thread, 4 px/row (float4)
#define TW 256
#define TH 16
#define SW (TW + 2)          // 258
#define SH (TH + 2)          // 18
#define BLKX (W / TW)        // 4
#define BLKY (H / TH)        // 64
#define PBLK (BLKX * BLKY)   // 256 partials per batch

// Per-block partial sums (s, s2): fully rewritten every launch -> no zeroing needed.
__device__ float2 g_part[BATCH * PBLK];
// Per-batch (mean, rstd): fully rewritten every launch.
__device__ float2 g_norm[BATCH];

__global__ __launch_bounds__(512)
void ltpe_pass1(const float* __restrict__ x, float* __restrict__ out) {
    __shared__ float gs[SH][SW];
    __shared__ float2 wred[16];

    const int b  = blockIdx.z;
    const int x0 = blockIdx.x * TW;
    const int y0 = blockIdx.y * TH;
    const int tx = threadIdx.x;          // 0..63
    const int ty = threadIdx.y;          // 0..7
    const int tid = ty * 64 + tx;

    const float* __restrict__ xr = x + (size_t)b * 3 * HW;
    const float* __restrict__ xg = xr + HW;
    const float* __restrict__ xb = xg + HW;

    // ---- Interior: 2 rows per thread, 6 float4 loads in flight, evict-first ----
    {
        const int gx = x0 + 4 * tx;
        const int o0 = (y0 + ty) * W + gx;
        const int o1 = (y0 + ty + 8) * W + gx;
        float4 r0 = __ldcs((const float4*)(xr + o0));
        float4 g0 = __ldcs((const float4*)(xg + o0));
        float4 b0 = __ldcs((const float4*)(xb + o0));
        float4 r1 = __ldcs((const float4*)(xr + o1));
        float4 g1 = __ldcs((const float4*)(xg + o1));
        float4 b1 = __ldcs((const float4*)(xb + o1));
        const int sc = 1 + 4 * tx;
        gs[ty + 1][sc + 0] = 0.3f * r0.x + 0.59f * g0.x + 0.11f * b0.x;
        gs[ty + 1][sc + 1] = 0.3f * r0.y + 0.59f * g0.y + 0.11f * b0.y;
        gs[ty + 1][sc + 2] = 0.3f * r0.z + 0.59f * g0.z + 0.11f * b0.z;
        gs[ty + 1][sc + 3] = 0.3f * r0.w + 0.59f * g0.w + 0.11f * b0.w;
        gs[ty + 9][sc + 0] = 0.3f * r1.x + 0.59f * g1.x + 0.11f * b1.x;
        gs[ty + 9][sc + 1] = 0.3f * r1.y + 0.59f * g1.y + 0.11f * b1.y;
        gs[ty + 9][sc + 2] = 0.3f * r1.z + 0.59f * g1.z + 0.11f * b1.z;
        gs[ty + 9][sc + 3] = 0.3f * r1.w + 0.59f * g1.w + 0.11f * b1.w;
    }

    // ---- Halo ring: 2*258 + 2*16 = 548 scalar loads ----
    for (int idx = tid; idx < 2 * SW + 2 * TH; idx += 512) {
        int sr, sc;
        if (idx < SW)              { sr = 0;      sc = idx; }
        else if (idx < 2 * SW)     { sr = SH - 1; sc = idx - SW; }
        else {
            int k = idx - 2 * SW;            // 0..31
            sr = (k & 15) + 1;
            sc = (k < TH) ? 0 : (SW - 1);
        }
        int gy = y0 + sr - 1;
        int gx = x0 + sc - 1;
        float v = 0.0f;
        if (gy >= 0 && gy < H && gx >= 0 && gx < W) {
            int o = gy * W + gx;
            v = 0.3f * __ldcs(xr + o) + 0.59f * __ldcs(xg + o) + 0.11f * __ldcs(xb + o);
        }
        gs[sr][sc] = v;
    }
    __syncthreads();

    // ---- Stencil: out = 0.5*(g+1) - (0.5/255) * sum_j 2^j * nb_j ----
    // weights: top(-1): -1:128, 0:64, +1:32 | mid: -1:1, +1:16 | bot(+1): -1:2, 0:4, +1:8
    float s = 0.0f, s2 = 0.0f;
    float* __restrict__ obase = out + (size_t)b * 3 * HW;
    const int sc0 = 1 + 4 * tx;

    #pragma unroll
    for (int rr = 0; rr < 2; rr++) {
        const int sr = ty + 1 + rr * 8;
        float t[6], m[6], bo[6];
        #pragma unroll
        for (int j = 0; j < 6; j++) {
            t[j]  = gs[sr - 1][sc0 - 1 + j];
            m[j]  = gs[sr    ][sc0 - 1 + j];
            bo[j] = gs[sr + 1][sc0 - 1 + j];
        }
        float4 ov;
        float* op = (float*)&ov;
        #pragma unroll
        for (int k = 0; k < 4; k++) {
            float g   = m[k + 1];
            float acc = 128.0f * t[k]  + 64.0f * t[k + 1] + 32.0f * t[k + 2]
                      +   1.0f * m[k]  + 16.0f * m[k + 2]
                      +   2.0f * bo[k] +  4.0f * bo[k + 1] + 8.0f * bo[k + 2];
            float o = 0.5f * (g + 1.0f) - (0.5f / 255.0f) * acc;
            op[k] = o;
            s  += o;
            s2 += o * o;
        }
        // scratch write: default policy -> stays in L2 for pass 2
        const int gy = y0 + ty + rr * 8;
        *(float4*)(obase + gy * W + x0 + 4 * tx) = ov;
    }

    // ---- Block reduction -> one float2 partial per block ----
    #pragma unroll
    for (int off = 16; off > 0; off >>= 1) {
        s  += __shfl_down_sync(0xFFFFFFFFu, s,  off);
        s2 += __shfl_down_sync(0xFFFFFFFFu, s2, off);
    }
    if ((tid & 31) == 0) wred[tid >> 5] = make_float2(s, s2);
    __syncthreads();
    if (tid == 0) {
        float ts = 0.0f, ts2 = 0.0f;
        #pragma unroll
        for (int w = 0; w < 16; w++) { ts += wred[w].x; ts2 += wred[w].y; }
        g_part[b * PBLK + blockIdx.y * BLKX + blockIdx.x] = make_float2(ts, ts2);
    }
}

// Tiny per-batch reduction: 8 blocks x 256 threads over 256 partials each.
__global__ __launch_bounds__(256)
void ltpe_norm(void) {
    __shared__ double rs[8], rs2[8];
    const int b   = blockIdx.x;
    const int tid = threadIdx.x;

    float2 p = g_part[b * PBLK + tid];
    double s  = (double)p.x;
    double s2 = (double)p.y;
    #pragma unroll
    for (int off = 16; off > 0; off >>= 1) {
        s  += __shfl_down_sync(0xFFFFFFFFu, s,  off);
        s2 += __shfl_down_sync(0xFFFFFFFFu, s2, off);
    }
    if ((tid & 31) == 0) { rs[tid >> 5] = s; rs2[tid >> 5] = s2; }
    __syncthreads();
    if (tid == 0) {
        double ts = 0.0, ts2 = 0.0;
        #pragma unroll
        for (int w = 0; w < 8; w++) { ts += rs[w]; ts2 += rs2[w]; }
        double mean = ts * (1.0 / HW);
        double var  = ts2 * (1.0 / HW) - mean * mean;
        g_norm[b] = make_float2((float)mean, rsqrtf((float)var + 1e-5f));
    }
}

// Pass 2: each thread handles 4 independent float4 chunks (MLP=4).
__global__ __launch_bounds__(256)
void ltpe_pass2(float* __restrict__ out) {
    const int b   = blockIdx.y;
    const int tid = threadIdx.x;

    const float2 nm  = g_norm[b];
    const float m    = nm.x;
    const float rstd = nm.y;

    float* __restrict__ base = out + (size_t)b * 3 * HW;
    const int i0 = blockIdx.x * (256 * 4 * 4);   // floats

    float4 v[4];
    #pragma unroll
    for (int k = 0; k < 4; k++)
        v[k] = __ldcs((const float4*)(base + i0 + (k * 256 + tid) * 4));

    #pragma unroll
    for (int k = 0; k < 4; k++) {
        v[k].x = (v[k].x - m) * rstd;
        v[k].y = (v[k].y - m) * rstd;
        v[k].z = (v[k].z - m) * rstd;
        v[k].w = (v[k].w - m) * rstd;
    }

    #pragma unroll
    for (int k = 0; k < 4; k++) {
        const int i = i0 + (k * 256 + tid) * 4;
        __stcs((float4*)(base + i),          v[k]);
        __stcs((float4*)(base + HW + i),     v[k]);
        __stcs((float4*)(base + 2 * HW + i), v[k]);
    }
}

extern "C" void kernel_launch(void* const* d_in, const int* in_sizes, int n_in,
                              void* d_out, int out_size) {
    const float* x = (const float*)d_in[0];
    float* out = (float*)d_out;

    dim3 blk1(64, 8);
    dim3 grd1(BLKX, BLKY, BATCH);
    ltpe_pass1<<<grd1, blk1>>>(x, out);

    ltpe_norm<<<BATCH, 256>>>();

    dim3 grd2(HW / 4 / 256 / 4, BATCH);   // 256 x 8
    ltpe_pass2<<<grd2, 256>>>(out);
}

// round 6
// speedup vs baseline: 1.3656x; 1.0309x over previous
#include <cuda_runtime.h>

#define BATCH 8
#define H 1024
#define W 1024
#define HW (H*W)

// Pass-1 tiling: 256 wide x 16 tall, 512 threads = (64,8), 2 rows/thread, 4 px/row
#define TW 256
#define TH 16
#define SH (TH + 2)          // 18 smem rows
#define SSTRIDE 264          // floats per smem row; interior at cols [4,260), halos at 3 and 260
#define BLKX (W / TW)        // 4
#define BLKY (H / TH)        // 64
#define PBLK (BLKX * BLKY)   // 256 partials per batch

__device__ float2 g_part[BATCH * PBLK];   // rewritten fully every launch
__device__ float2 g_norm[BATCH];          // rewritten fully every launch

__device__ __forceinline__ float gray3(float r, float g, float b) {
    return 0.3f * r + 0.59f * g + 0.11f * b;
}

__global__ __launch_bounds__(512)
void ltpe_pass1(const float* __restrict__ x, float* __restrict__ out) {
    __shared__ float gs[SH * SSTRIDE];
    __shared__ float2 wred[16];

    const int b  = blockIdx.z;
    const int x0 = blockIdx.x * TW;
    const int y0 = blockIdx.y * TH;
    const int tx = threadIdx.x;          // 0..63
    const int ty = threadIdx.y;          // 0..7
    const int tid = ty * 64 + tx;

    const float* __restrict__ xr = x + (size_t)b * 3 * HW;
    const float* __restrict__ xg = xr + HW;
    const float* __restrict__ xb = xg + HW;

    // ---- Interior: 2 rows/thread, 6 float4 LDG in flight, vector STS ----
    {
        const int gx = x0 + 4 * tx;
        const int o0 = (y0 + ty) * W + gx;
        const int o1 = (y0 + ty + 8) * W + gx;
        float4 r0 = __ldcs((const float4*)(xr + o0));
        float4 g0 = __ldcs((const float4*)(xg + o0));
        float4 b0 = __ldcs((const float4*)(xb + o0));
        float4 r1 = __ldcs((const float4*)(xr + o1));
        float4 g1 = __ldcs((const float4*)(xg + o1));
        float4 b1 = __ldcs((const float4*)(xb + o1));
        float4 q0 = make_float4(gray3(r0.x, g0.x, b0.x), gray3(r0.y, g0.y, b0.y),
                                gray3(r0.z, g0.z, b0.z), gray3(r0.w, g0.w, b0.w));
        float4 q1 = make_float4(gray3(r1.x, g1.x, b1.x), gray3(r1.y, g1.y, b1.y),
                                gray3(r1.z, g1.z, b1.z), gray3(r1.w, g1.w, b1.w));
        *(float4*)(gs + (ty + 1) * SSTRIDE + 4 + 4 * tx) = q0;   // 16B-aligned
        *(float4*)(gs + (ty + 9) * SSTRIDE + 4 + 4 * tx) = q1;
    }

    // ---- Row halos (rows 0 and 17): coalesced float4, tids 0..127 ----
    if (tid < 128) {
        const int top = (tid < 64);
        const int lt  = top ? tid : (tid - 64);
        const int gy  = top ? (y0 - 1) : (y0 + TH);
        const int srow = top ? 0 : (SH - 1);
        float4 q = make_float4(0.f, 0.f, 0.f, 0.f);
        if (gy >= 0 && gy < H) {
            const int o = gy * W + x0 + 4 * lt;
            float4 r4 = __ldcs((const float4*)(xr + o));
            float4 g4 = __ldcs((const float4*)(xg + o));
            float4 b4 = __ldcs((const float4*)(xb + o));
            q = make_float4(gray3(r4.x, g4.x, b4.x), gray3(r4.y, g4.y, b4.y),
                            gray3(r4.z, g4.z, b4.z), gray3(r4.w, g4.w, b4.w));
        }
        *(float4*)(gs + srow * SSTRIDE + 4 + 4 * lt) = q;
    }
    // ---- Column halos (cols 3 and 260, all 18 rows): tids 128..163 ----
    else if (tid < 128 + 2 * SH) {
        const int j   = tid - 128;          // 0..35
        const int sr  = j >> 1;             // 0..17
        const int rgt = j & 1;
        const int gy  = y0 + sr - 1;
        const int gx  = rgt ? (x0 + TW) : (x0 - 1);
        float v = 0.0f;
        if (gy >= 0 && gy < H && gx >= 0 && gx < W) {
            const int o = gy * W + gx;
            v = gray3(__ldcs(xr + o), __ldcs(xg + o), __ldcs(xb + o));
        }
        gs[sr * SSTRIDE + (rgt ? 260 : 3)] = v;
    }
    __syncthreads();

    // ---- Stencil: out = 0.5*(g+1) - (0.5/255)*[128t-1 +64t0 +32t+1 +1mL +16mR +2b-1 +4b0 +8b+1]
    float s = 0.0f, s2 = 0.0f;
    float* __restrict__ obase = out + (size_t)b * 3 * HW;
    const int cbase = 4 * tx;               // smem col of left scalar = cbase+3

    #pragma unroll
    for (int rr = 0; rr < 2; rr++) {
        const int oy = ty + rr * 8;         // output row in tile (0..15)
        const float* rT = gs + (oy    ) * SSTRIDE + cbase;
        const float* rM = gs + (oy + 1) * SSTRIDE + cbase;
        const float* rB = gs + (oy + 2) * SSTRIDE + cbase;
        // 6 cols per row: scalar[3], float4[4..7], scalar[8]
        float  tL = rT[3];            float4 t4 = *(const float4*)(rT + 4); float tR = rT[8];
        float  mL = rM[3];            float4 m4 = *(const float4*)(rM + 4); float mR = rM[8];
        float  bL = rB[3];            float4 b4 = *(const float4*)(rB + 4); float bR = rB[8];
        float t[6] = {tL, t4.x, t4.y, t4.z, t4.w, tR};
        float m[6] = {mL, m4.x, m4.y, m4.z, m4.w, mR};
        float bo[6] = {bL, b4.x, b4.y, b4.z, b4.w, bR};

        float4 ov;
        float* op = (float*)&ov;
        #pragma unroll
        for (int k = 0; k < 4; k++) {
            float g   = m[k + 1];
            float acc = 128.0f * t[k]  + 64.0f * t[k + 1] + 32.0f * t[k + 2]
                      +   1.0f * m[k]  + 16.0f * m[k + 2]
                      +   2.0f * bo[k] +  4.0f * bo[k + 1] + 8.0f * bo[k + 2];
            float o = 0.5f * (g + 1.0f) - (0.5f / 255.0f) * acc;
            op[k] = o;
            s  += o;
            s2 += o * o;
        }
        // scratch write: default policy -> stays in L2 for pass 2
        *(float4*)(obase + (y0 + oy) * W + x0 + 4 * tx) = ov;
    }

    // ---- Block reduction -> one float2 partial per block ----
    #pragma unroll
    for (int off = 16; off > 0; off >>= 1) {
        s  += __shfl_down_sync(0xFFFFFFFFu, s,  off);
        s2 += __shfl_down_sync(0xFFFFFFFFu, s2, off);
    }
    if ((tid & 31) == 0) wred[tid >> 5] = make_float2(s, s2);
    __syncthreads();
    if (tid == 0) {
        float ts = 0.0f, ts2 = 0.0f;
        #pragma unroll
        for (int w = 0; w < 16; w++) { ts += wred[w].x; ts2 += wred[w].y; }
        g_part[b * PBLK + blockIdx.y * BLKX + blockIdx.x] = make_float2(ts, ts2);
    }
}

// Tiny per-batch reduction: 8 blocks x 256 threads over 256 partials each.
__global__ __launch_bounds__(256)
void ltpe_norm(void) {
    __shared__ double rs[8], rs2[8];
    const int b   = blockIdx.x;
    const int tid = threadIdx.x;

    float2 p = g_part[b * PBLK + tid];
    double s  = (double)p.x;
    double s2 = (double)p.y;
    #pragma unroll
    for (int off = 16; off > 0; off >>= 1) {
        s  += __shfl_down_sync(0xFFFFFFFFu, s,  off);
        s2 += __shfl_down_sync(0xFFFFFFFFu, s2, off);
    }
    if ((tid & 31) == 0) { rs[tid >> 5] = s; rs2[tid >> 5] = s2; }
    __syncthreads();
    if (tid == 0) {
        double ts = 0.0, ts2 = 0.0;
        #pragma unroll
        for (int w = 0; w < 8; w++) { ts += rs[w]; ts2 += rs2[w]; }
        double mean = ts * (1.0 / HW);
        double var  = ts2 * (1.0 / HW) - mean * mean;
        g_norm[b] = make_float2((float)mean, rsqrtf((float)var + 1e-5f));
    }
}

// Pass 2: each thread handles 4 independent float4 chunks (MLP=4).
__global__ __launch_bounds__(256)
void ltpe_pass2(float* __restrict__ out) {
    const int b   = blockIdx.y;
    const int tid = threadIdx.x;

    const float2 nm  = g_norm[b];
    const float m    = nm.x;
    const float rstd = nm.y;

    float* __restrict__ base = out + (size_t)b * 3 * HW;
    const int i0 = blockIdx.x * (256 * 4 * 4);   // floats

    float4 v[4];
    #pragma unroll
    for (int k = 0; k < 4; k++)
        v[k] = __ldcs((const float4*)(base + i0 + (k * 256 + tid) * 4));

    #pragma unroll
    for (int k = 0; k < 4; k++) {
        v[k].x = (v[k].x - m) * rstd;
        v[k].y = (v[k].y - m) * rstd;
        v[k].z = (v[k].z - m) * rstd;
        v[k].w = (v[k].w - m) * rstd;
    }

    #pragma unroll
    for (int k = 0; k < 4; k++) {
        const int i = i0 + (k * 256 + tid) * 4;
        __stcs((float4*)(base + i),          v[k]);
        __stcs((float4*)(base + HW + i),     v[k]);
        __stcs((float4*)(base + 2 * HW + i), v[k]);
    }
}

extern "C" void kernel_launch(void* const* d_in, const int* in_sizes, int n_in,
                              void* d_out, int out_size) {
    const float* x = (const float*)d_in[0];
    float* out = (float*)d_out;

    dim3 blk1(64, 8);
    dim3 grd1(BLKX, BLKY, BATCH);
    ltpe_pass1<<<grd1, blk1>>>(x, out);

    ltpe_norm<<<BATCH, 256>>>();

    dim3 grd2(HW / 4 / 256 / 4, BATCH);   // 256 x 8
    ltpe_pass2<<<grd2, 256>>>(out);
}

// round 9
// speedup vs baseline: 1.3798x; 1.0104x over previous
#include <cuda_runtime.h>

#define BATCH 8
#define H 1024
#define W 1024
#define HW (H*W)

// Pass-1 tiling: 256 wide x 16 tall, 512 threads = (64,8), 2 CONSECUTIVE rows/thread
#define TW 256
#define TH 16
#define SH (TH + 2)          // 18 smem rows
#define SSTRIDE 264          // floats per smem row; interior cols [4,260), halo scalars at 3 / 260
#define BLKX (W / TW)        // 4
#define BLKY (H / TH)        // 64
#define PBLK (BLKX * BLKY)   // 256 partials per batch

__device__ float2 g_part[BATCH * PBLK];   // rewritten fully every launch
__device__ float2 g_norm[BATCH];          // rewritten fully every launch

__device__ __forceinline__ float gray3(float r, float g, float b) {
    return 0.3f * r + 0.59f * g + 0.11f * b;
}

// One stencil output: rows (t, m, b) each given as {L, v4, R}, output column k (0..3).
__device__ __forceinline__ float stencil1(
    float tL, float4 t4, float tR,
    float mL, float4 m4, float mR,
    float bL, float4 b4, float bR,
    int k)
{
    float t[6]  = {tL, t4.x, t4.y, t4.z, t4.w, tR};
    float m[6]  = {mL, m4.x, m4.y, m4.z, m4.w, mR};
    float bo[6] = {bL, b4.x, b4.y, b4.z, b4.w, bR};
    float g   = m[k + 1];
    float acc = 128.0f * t[k]  + 64.0f * t[k + 1] + 32.0f * t[k + 2]
              +   1.0f * m[k]  + 16.0f * m[k + 2]
              +   2.0f * bo[k] +  4.0f * bo[k + 1] + 8.0f * bo[k + 2];
    return 0.5f * (g + 1.0f) - (0.5f / 255.0f) * acc;
}

__global__ __launch_bounds__(512)
void ltpe_pass1(const float* __restrict__ x, float* __restrict__ out) {
    __shared__ float gs[SH * SSTRIDE];
    __shared__ float2 wred[16];

    const int b    = blockIdx.z;
    const int x0   = blockIdx.x * TW;
    const int y0   = blockIdx.y * TH;
    const int tx   = threadIdx.x;          // 0..63
    const int ty   = threadIdx.y;          // 0..7
    const int tid  = ty * 64 + tx;
    const int lane = tid & 31;
    const int cbase = 4 * tx;              // left edge scalar at smem col cbase+3

    const float* __restrict__ xr = x + (size_t)b * 3 * HW;
    const float* __restrict__ xg = xr + HW;
    const float* __restrict__ xb = xg + HW;

    // ---- Interior: 2 consecutive rows/thread, 6 float4 LDG in flight ----
    const int r0 = 2 * ty;                 // tile rows r0, r0+1 (smem rows r0+1, r0+2)
    float4 q0, q1;
    {
        const int gx = x0 + 4 * tx;
        const int o0 = (y0 + r0) * W + gx;
        const int o1 = o0 + W;
        float4 ra = __ldcs((const float4*)(xr + o0));
        float4 ga = __ldcs((const float4*)(xg + o0));
        float4 ba = __ldcs((const float4*)(xb + o0));
        float4 rb = __ldcs((const float4*)(xr + o1));
        float4 gb = __ldcs((const float4*)(xg + o1));
        float4 bb = __ldcs((const float4*)(xb + o1));
        q0 = make_float4(gray3(ra.x, ga.x, ba.x), gray3(ra.y, ga.y, ba.y),
                         gray3(ra.z, ga.z, ba.z), gray3(ra.w, ga.w, ba.w));
        q1 = make_float4(gray3(rb.x, gb.x, bb.x), gray3(rb.y, gb.y, bb.y),
                         gray3(rb.z, gb.z, bb.z), gray3(rb.w, gb.w, bb.w));
        *(float4*)(gs + (r0 + 1) * SSTRIDE + 4 + cbase) = q0;
        *(float4*)(gs + (r0 + 2) * SSTRIDE + 4 + cbase) = q1;
    }

    // ---- Row halos (smem rows 0 and 17): coalesced float4, tids 0..127 ----
    if (tid < 128) {
        const int top  = (tid < 64);
        const int lt   = top ? tid : (tid - 64);
        const int gy   = top ? (y0 - 1) : (y0 + TH);
        const int srow = top ? 0 : (SH - 1);
        float4 q = make_float4(0.f, 0.f, 0.f, 0.f);
        if (gy >= 0 && gy < H) {
            const int o = gy * W + x0 + 4 * lt;
            float4 r4 = __ldcs((const float4*)(xr + o));
            float4 g4 = __ldcs((const float4*)(xg + o));
            float4 b4 = __ldcs((const float4*)(xb + o));
            q = make_float4(gray3(r4.x, g4.x, b4.x), gray3(r4.y, g4.y, b4.y),
                            gray3(r4.z, g4.z, b4.z), gray3(r4.w, g4.w, b4.w));
        }
        *(float4*)(gs + srow * SSTRIDE + 4 + 4 * lt) = q;
    }
    // ---- Column halos (cols 3 and 260, all 18 rows): tids 128..163 ----
    else if (tid < 128 + 2 * SH) {
        const int j   = tid - 128;          // 0..35
        const int sr  = j >> 1;             // 0..17
        const int rgt = j & 1;
        const int gy  = y0 + sr - 1;
        const int gx  = rgt ? (x0 + TW) : (x0 - 1);
        float v = 0.0f;
        if (gy >= 0 && gy < H && gx >= 0 && gx < W) {
            const int o = gy * W + gx;
            v = gray3(__ldcs(xr + o), __ldcs(xg + o), __ldcs(xb + o));
        }
        gs[sr * SSTRIDE + (rgt ? 260 : 3)] = v;
    }
    __syncthreads();

    // ---- Fetch only the two vertical-neighbor rows from smem ----
    float4 t4 = *(const float4*)(gs + (r0    ) * SSTRIDE + 4 + cbase);  // row above pair
    float4 b4 = *(const float4*)(gs + (r0 + 3) * SSTRIDE + 4 + cbase);  // row below pair

    // ---- Edge scalars via register shuffles; warp-boundary lanes fall back to smem ----
    const unsigned FULL = 0xFFFFFFFFu;
    float tLs  = __shfl_up_sync  (FULL, t4.w, 1);
    float tRs  = __shfl_down_sync(FULL, t4.x, 1);
    float m0Ls = __shfl_up_sync  (FULL, q0.w, 1);
    float m0Rs = __shfl_down_sync(FULL, q0.x, 1);
    float m1Ls = __shfl_up_sync  (FULL, q1.w, 1);
    float m1Rs = __shfl_down_sync(FULL, q1.x, 1);
    float bLs  = __shfl_up_sync  (FULL, b4.w, 1);
    float bRs  = __shfl_down_sync(FULL, b4.x, 1);

    const bool l0  = (lane == 0);
    const bool l31 = (lane == 31);
    float tL  = l0  ? gs[(r0    ) * SSTRIDE + cbase + 3] : tLs;
    float m0L = l0  ? gs[(r0 + 1) * SSTRIDE + cbase + 3] : m0Ls;
    float m1L = l0  ? gs[(r0 + 2) * SSTRIDE + cbase + 3] : m1Ls;
    float bL  = l0  ? gs[(r0 + 3) * SSTRIDE + cbase + 3] : bLs;
    float tR  = l31 ? gs[(r0    ) * SSTRIDE + cbase + 8] : tRs;
    float m0R = l31 ? gs[(r0 + 1) * SSTRIDE + cbase + 8] : m0Rs;
    float m1R = l31 ? gs[(r0 + 2) * SSTRIDE + cbase + 8] : m1Rs;
    float bR  = l31 ? gs[(r0 + 3) * SSTRIDE + cbase + 8] : bRs;

    // ---- Stencil rows 2ty and 2ty+1 (middle rows come from registers) ----
    float s = 0.0f, s2 = 0.0f;
    float* __restrict__ obase = out + (size_t)b * 3 * HW;

    float4 ov0, ov1;
    float* op0 = (float*)&ov0;
    float* op1 = (float*)&ov1;
    #pragma unroll
    for (int k = 0; k < 4; k++) {
        float o0 = stencil1(tL,  t4, tR,   m0L, q0, m0R,  m1L, q1, m1R, k);
        float o1 = stencil1(m0L, q0, m0R,  m1L, q1, m1R,  bL,  b4, bR,  k);
        op0[k] = o0; op1[k] = o1;
        s  += o0 + o1;
        s2 += o0 * o0 + o1 * o1;
    }
    // scratch writes: default policy -> stays in L2 for pass 2
    *(float4*)(obase + (y0 + r0    ) * W + x0 + cbase) = ov0;
    *(float4*)(obase + (y0 + r0 + 1) * W + x0 + cbase) = ov1;

    // ---- Block reduction -> one float2 partial per block ----
    #pragma unroll
    for (int off = 16; off > 0; off >>= 1) {
        s  += __shfl_down_sync(FULL, s,  off);
        s2 += __shfl_down_sync(FULL, s2, off);
    }
    if (lane == 0) wred[tid >> 5] = make_float2(s, s2);
    __syncthreads();
    if (tid == 0) {
        float ts = 0.0f, ts2 = 0.0f;
        #pragma unroll
        for (int w = 0; w < 16; w++) { ts += wred[w].x; ts2 += wred[w].y; }
        g_part[b * PBLK + blockIdx.y * BLKX + blockIdx.x] = make_float2(ts, ts2);
    }
}

// Tiny per-batch reduction: 8 blocks x 256 threads over 256 partials each.
__global__ __launch_bounds__(256)
void ltpe_norm(void) {
    __shared__ double rs[8], rs2[8];
    const int b   = blockIdx.x;
    const int tid = threadIdx.x;

    float2 p = g_part[b * PBLK + tid];
    double s  = (double)p.x;
    double s2 = (double)p.y;
    #pragma unroll
    for (int off = 16; off > 0; off >>= 1) {
        s  += __shfl_down_sync(0xFFFFFFFFu, s,  off);
        s2 += __shfl_down_sync(0xFFFFFFFFu, s2, off);
    }
    if ((tid & 31) == 0) { rs[tid >> 5] = s; rs2[tid >> 5] = s2; }
    __syncthreads();
    if (tid == 0) {
        double ts = 0.0, ts2 = 0.0;
        #pragma unroll
        for (int w = 0; w < 8; w++) { ts += rs[w]; ts2 += rs2[w]; }
        double mean = ts * (1.0 / HW);
        double var  = ts2 * (1.0 / HW) - mean * mean;
        g_norm[b] = make_float2((float)mean, rsqrtf((float)var + 1e-5f));
    }
}

// Pass 2: each thread handles 4 independent float4 chunks (MLP=4).
__global__ __launch_bounds__(256)
void ltpe_pass2(float* __restrict__ out) {
    const int b   = blockIdx.y;
    const int tid = threadIdx.x;

    const float2 nm  = g_norm[b];
    const float m    = nm.x;
    const float rstd = nm.y;

    float* __restrict__ base = out + (size_t)b * 3 * HW;
    const int i0 = blockIdx.x * (256 * 4 * 4);   // floats

    float4 v[4];
    #pragma unroll
    for (int k = 0; k < 4; k++)
        v[k] = __ldcs((const float4*)(base + i0 + (k * 256 + tid) * 4));

    #pragma unroll
    for (int k = 0; k < 4; k++) {
        v[k].x = (v[k].x - m) * rstd;
        v[k].y = (v[k].y - m) * rstd;
        v[k].z = (v[k].z - m) * rstd;
        v[k].w = (v[k].w - m) * rstd;
    }

    #pragma unroll
    for (int k = 0; k < 4; k++) {
        const int i = i0 + (k * 256 + tid) * 4;
        __stcs((float4*)(base + i),          v[k]);
        __stcs((float4*)(base + HW + i),     v[k]);
        __stcs((float4*)(base + 2 * HW + i), v[k]);
    }
}

extern "C" void kernel_launch(void* const* d_in, const int* in_sizes, int n_in,
                              void* d_out, int out_size) {
    const float* x = (const float*)d_in[0];
    float* out = (float*)d_out;

    dim3 blk1(64, 8);
    dim3 grd1(BLKX, BLKY, BATCH);
    ltpe_pass1<<<grd1, blk1>>>(x, out);

    ltpe_norm<<<BATCH, 256>>>();

    dim3 grd2(HW / 4 / 256 / 4, BATCH);   // 256 x 8
    ltpe_pass2<<<grd2, 256>>>(out);
}